// round 16
// baseline (speedup 1.0000x reference)
#include <cuda_runtime.h>
#include <cuda_bf16.h>
#include <math.h>
#include <stdint.h>

#define BATCH 64
#define NCAPS 2048
#define IDIM 16
#define DOUT 256
#define MLAN 48
#define KSPLIT 3

typedef unsigned long long u64;

__device__ float g_u[(size_t)BATCH * NCAPS * DOUT];              // 134 MB
__device__ float g_C[(size_t)BATCH * DOUT * DOUT];               // 16 MB
__device__ float g_Cp[KSPLIT][(size_t)BATCH * DOUT * DOUT];      // 48 MB partials
// transposed bf16 splits: [b][d][c], c contiguous
__device__ __nv_bfloat16 g_uthi[(size_t)BATCH * DOUT * NCAPS];   // 64 MB
__device__ __nv_bfloat16 g_utmid[(size_t)BATCH * DOUT * NCAPS];  // 64 MB
__device__ __nv_bfloat16 g_utlo[(size_t)BATCH * DOUT * NCAPS];   // 64 MB

__device__ __forceinline__ uint32_t smem_u32(const void* p) {
    uint32_t a;
    asm("{ .reg .u64 t; cvta.to.shared.u64 t, %1; cvt.u32.u64 %0, t; }"
        : "=r"(a) : "l"(p));
    return a;
}
#define SW128(off) ((off) ^ (((off) >> 3) & 0x70))

__device__ __forceinline__ void ldmx4(uint32_t* r, uint32_t addr) {
    asm volatile("ldmatrix.sync.aligned.m8n8.x4.shared.b16 {%0,%1,%2,%3}, [%4];"
                 : "=r"(r[0]), "=r"(r[1]), "=r"(r[2]), "=r"(r[3]) : "r"(addr));
}
__device__ __forceinline__ void mma16816(float* d, const uint32_t* a, const uint32_t* b) {
    asm volatile("mma.sync.aligned.m16n8k16.row.col.f32.bf16.bf16.f32 "
                 "{%0,%1,%2,%3}, {%4,%5,%6,%7}, {%8,%9}, {%0,%1,%2,%3};"
                 : "+f"(d[0]), "+f"(d[1]), "+f"(d[2]), "+f"(d[3])
                 : "r"(a[0]), "r"(a[1]), "r"(a[2]), "r"(a[3]), "r"(b[0]), "r"(b[1]));
}

// ---------------------------------------------------------------------------
// Pass 1: u[b,c,o] = sum_i caps[b,c,i] * W[c,i,o]
// ---------------------------------------------------------------------------
__global__ void u_kernel(const float* __restrict__ caps, const float* __restrict__ W)
{
    int c  = blockIdx.x;
    int b0 = blockIdx.y * 32;
    __shared__ __align__(16) float caps_s[32][IDIM];
    __shared__ __align__(16) float w_s[IDIM][DOUT];
    int t = threadIdx.x;

    for (int idx = t; idx < 32 * IDIM; idx += 256) {
        int b = idx >> 4, i = idx & 15;
        caps_s[b][i] = caps[(size_t)(b0 + b) * (NCAPS * IDIM) + (size_t)c * IDIM + i];
    }
    for (int idx = t; idx < IDIM * DOUT; idx += 256)
        ((float*)w_s)[idx] = W[(size_t)c * (IDIM * DOUT) + idx];
    __syncthreads();

    float wr[IDIM];
#pragma unroll
    for (int i = 0; i < IDIM; i++) wr[i] = w_s[i][t];

#pragma unroll 4
    for (int b = 0; b < 32; b++) {
        const float4* cp = (const float4*)caps_s[b];
        float acc = 0.f;
#pragma unroll
        for (int q = 0; q < 4; q++) {
            float4 cv = cp[q];
            acc += cv.x * wr[q * 4 + 0] + cv.y * wr[q * 4 + 1]
                 + cv.z * wr[q * 4 + 2] + cv.w * wr[q * 4 + 3];
        }
        g_u[(size_t)(b0 + b) * (NCAPS * DOUT) + (size_t)c * DOUT + t] = acc;
    }
}

// ---------------------------------------------------------------------------
// Pass 1.5: transpose + 3-way bf16 split
// ---------------------------------------------------------------------------
__global__ void split_kernel()
{
    __shared__ float ft[64][65];
    int c0 = blockIdx.x * 64;
    int d0 = blockIdx.y * 64;
    int b  = blockIdx.z;
    int t  = threadIdx.x;

    const float* ub = g_u + (size_t)b * NCAPS * DOUT;
#pragma unroll
    for (int i = t; i < 4096; i += 256) {
        int r = i >> 6, cc = i & 63;
        ft[r][cc] = ub[(size_t)(c0 + r) * DOUT + d0 + cc];
    }
    __syncthreads();

    size_t obase = ((size_t)b * DOUT + d0) * NCAPS + c0;
#pragma unroll
    for (int i = t; i < 4096; i += 256) {
        int dr = i >> 6, cc = i & 63;
        float x = ft[cc][dr];
        __nv_bfloat16 hi = __float2bfloat16(x);
        float r1 = x - __bfloat162float(hi);
        __nv_bfloat16 mid = __float2bfloat16(r1);
        float r2 = r1 - __bfloat162float(mid);
        __nv_bfloat16 lo = __float2bfloat16(r2);
        size_t off = obase + (size_t)dr * NCAPS + cc;
        g_uthi[off]  = hi;
        g_utmid[off] = mid;
        g_utlo[off]  = lo;
    }
}

// ---------------------------------------------------------------------------
// Pass 2: SYRK via mma.sync bf16 3-split (6 products), 128x128 tiles.
// grid (3 tiles, KSPLIT, BATCH), 256 threads = 8 warps of 32x64 warp tiles.
// ---------------------------------------------------------------------------
#define SMEM_TILE0 0
#define TILE_B 16384
#define SYRK_SMEM (6 * TILE_B)

__global__ void __launch_bounds__(256, 2) syrk_mma_kernel()
{
    extern __shared__ char smem[];
    uint32_t sb = smem_u32(smem);
    int t = threadIdx.x;
    int w = t >> 5, lane = t & 31;

    int which = blockIdx.x;              // 0:(0,0) 1:(1,1) 2:(1,0)
    int ks    = blockIdx.y;
    int b     = blockIdx.z;
    int d0 = (which == 0) ? 0 : 128;
    int e0 = (which == 1) ? 128 : 0;
    bool diag = (which != 2);
    int it0 = (ks == 0) ? 0 : (ks == 1) ? 11 : 22;
    int it1 = (ks == 0) ? 11 : (ks == 1) ? 22 : 32;

    int m0 = (w >> 1) * 32;              // warp row within 128
    int n0 = (w & 1) * 64;               // warp col within 128

    const __nv_bfloat16* srcs[3] = {g_uthi, g_utmid, g_utlo};
    int ntile = diag ? 3 : 6;

    float acc[2][8][4];
#pragma unroll
    for (int i = 0; i < 2; i++)
#pragma unroll
        for (int j = 0; j < 8; j++)
#pragma unroll
            for (int k = 0; k < 4; k++) acc[i][j][k] = 0.f;

    // precompute per-lane ldmatrix address components
    int a_row = (lane & 7) + ((lane >> 3) & 1) * 8;   // + m tile base
    int a_col = (lane >> 4) * 8;                      // + kb
    int b_row = (lane & 7) + (lane >> 4) * 8;         // + n tile base
    int b_col = ((lane >> 3) & 1) * 8;                // + kb

    const int pa[6] = {0, 0, 1, 1, 0, 2};
    const int pb[6] = {0, 1, 0, 1, 2, 0};

    for (int it = it0; it < it1; it++) {
        int c0 = it * 64;
        // stage tiles: 128 rows x 64 bf16 (128B/row), SW128 swizzled
        for (int tile = 0; tile < ntile; tile++) {
            const __nv_bfloat16* src = srcs[tile % 3]
                + ((size_t)b * DOUT + (tile < 3 ? d0 : e0)) * NCAPS + c0;
            char* dst = smem + tile * TILE_B;
#pragma unroll 4
            for (int i = t; i < 1024; i += 256) {
                int r = i >> 3, q = i & 7;
                uint4 v = *(const uint4*)(src + (size_t)r * NCAPS + q * 8);
                uint32_t off = r * 128 + q * 16;
                *(uint4*)(dst + SW128(off)) = v;
            }
        }
        __syncthreads();

#pragma unroll
        for (int p = 0; p < 6; p++) {
            uint32_t abase = sb + pa[p] * TILE_B;
            uint32_t bbase = sb + (diag ? pb[p] : (3 + pb[p])) * TILE_B;
#pragma unroll
            for (int kb = 0; kb < 64; kb += 16) {
                uint32_t af[2][4];
#pragma unroll
                for (int mt = 0; mt < 2; mt++) {
                    uint32_t off = (uint32_t)(m0 + mt * 16 + a_row) * 128
                                 + (uint32_t)(kb + a_col) * 2;
                    ldmx4(af[mt], abase + SW128(off));
                }
#pragma unroll
                for (int ng = 0; ng < 4; ng++) {
                    uint32_t bf[4];
                    uint32_t off = (uint32_t)(n0 + ng * 16 + b_row) * 128
                                 + (uint32_t)(kb + b_col) * 2;
                    ldmx4(bf, bbase + SW128(off));
#pragma unroll
                    for (int mt = 0; mt < 2; mt++) {
                        mma16816(acc[mt][ng * 2],     af[mt], bf);
                        mma16816(acc[mt][ng * 2 + 1], af[mt], bf + 2);
                    }
                }
            }
        }
        __syncthreads();
    }

    // epilogue: write warp tile to partial buffer
    float* Cb = g_Cp[ks] + (size_t)b * DOUT * DOUT;
    int lr = lane >> 2, lc = (lane & 3) * 2;
#pragma unroll
    for (int mt = 0; mt < 2; mt++) {
#pragma unroll
        for (int nf = 0; nf < 8; nf++) {
            int row = d0 + m0 + mt * 16 + lr;
            int col = e0 + n0 + nf * 8 + lc;
            *(float2*)&Cb[(size_t)row * DOUT + col] =
                make_float2(acc[mt][nf][0], acc[mt][nf][1]);
            *(float2*)&Cb[(size_t)(row + 8) * DOUT + col] =
                make_float2(acc[mt][nf][2], acc[mt][nf][3]);
        }
    }
}

// sum the 3 K-split partials (deterministic)
__global__ void reduce_kernel()
{
    int b = blockIdx.y;
    int which = blockIdx.x;
    int d0 = (which == 0) ? 0 : 128;
    int e0 = (which == 1) ? 128 : 0;
    size_t base = (size_t)b * DOUT * DOUT;
    int t = threadIdx.x;
    for (int i = t; i < 128 * 32; i += 256) {
        int r = i >> 5, c4 = (i & 31);
        size_t off = base + (size_t)(d0 + r) * DOUT + e0 + c4 * 4;
        float4 a = *(const float4*)&g_Cp[0][off];
        float4 bb = *(const float4*)&g_Cp[1][off];
        float4 c = *(const float4*)&g_Cp[2][off];
        float4 s = make_float4(a.x + bb.x + c.x, a.y + bb.y + c.y,
                               a.z + bb.z + c.z, a.w + bb.w + c.w);
        *(float4*)&g_C[off] = s;
    }
}

// mirror (1,0) tile into (0,1)
__global__ void mirror_kernel()
{
    __shared__ float tile[32][33];
    float* Cb = g_C + (size_t)blockIdx.z * DOUT * DOUT;
    int sx = 128 + blockIdx.x * 32;
    int sy = blockIdx.y * 32;
    int tx = threadIdx.x, ty = threadIdx.y;
#pragma unroll
    for (int k = 0; k < 32; k += 8)
        tile[ty + k][tx] = Cb[(size_t)(sx + ty + k) * DOUT + sy + tx];
    __syncthreads();
#pragma unroll
    for (int k = 0; k < 32; k += 8)
        Cb[(size_t)(sy + ty + k) * DOUT + sx + tx] = tile[tx][ty + k];
}

// ---------------------------------------------------------------------------
// Pass 3: Lanczos(m=48), 512 threads/block, CGS1, parallel Sturm.
// ---------------------------------------------------------------------------
#define NWARP 16
__device__ __forceinline__ float blk_sum512(float v, float* red)
{
#pragma unroll
    for (int o = 16; o; o >>= 1) v += __shfl_xor_sync(0xffffffffu, v, o);
    int lane = threadIdx.x & 31, wid = threadIdx.x >> 5;
    __syncthreads();
    if (lane == 0) red[wid] = v;
    __syncthreads();
    float s = red[0];
#pragma unroll
    for (int i = 1; i < NWARP; i++) s += red[i];
    return s;
}

__device__ __forceinline__ float blk_max512(float v, float* red)
{
#pragma unroll
    for (int o = 16; o; o >>= 1) v = fmaxf(v, __shfl_xor_sync(0xffffffffu, v, o));
    int lane = threadIdx.x & 31, wid = threadIdx.x >> 5;
    __syncthreads();
    if (lane == 0) red[wid] = v;
    __syncthreads();
    float s = red[0];
#pragma unroll
    for (int i = 1; i < NWARP; i++) s = fmaxf(s, red[i]);
    return s;
}

__device__ __forceinline__ float blk_min512(float v, float* red)
{
#pragma unroll
    for (int o = 16; o; o >>= 1) v = fminf(v, __shfl_xor_sync(0xffffffffu, v, o));
    int lane = threadIdx.x & 31, wid = threadIdx.x >> 5;
    __syncthreads();
    if (lane == 0) red[wid] = v;
    __syncthreads();
    float s = red[0];
#pragma unroll
    for (int i = 1; i < NWARP; i++) s = fminf(s, red[i]);
    return s;
}

__global__ void __launch_bounds__(512, 1) lanczos_kernel(float* __restrict__ out)
{
    extern __shared__ float sh[];
    float* V     = sh;
    float* wv    = V + (MLAN + 1) * 256;
    float* cbuf  = wv + 256;
    float* alpha = cbuf + 512;
    float* beta  = alpha + MLAN;
    float* coef  = beta + MLAN;
    float* yv    = coef + MLAN;
    float* tdd   = yv + MLAN;
    float* tu1   = tdd + MLAN;
    float* tu2   = tu1 + MLAN;
    float* red   = tu2 + MLAN;
    float* ssc   = red + NWARP;

    __shared__ int midx;

    int t = threadIdx.x;
    int lane = t & 31, wid = t >> 5;
    int e = t & 255;
    int half = t >> 8;
    int b = blockIdx.x;
    const float* C = g_C + (size_t)b * DOUT * DOUT;

    float x = __sinf((float)e * 1.7f + 0.5f) + 0.01f;
    float nn = blk_sum512((t < 256) ? x * x : 0.f, red);
    x *= rsqrtf(nn);
    if (t < 256) V[t] = x;
    __syncthreads();

    int m_eff = MLAN;
    int rbase = wid * 16;
    for (int j = 0; j < MLAN; j++) {
        {
            const float4* v4 = (const float4*)(V + j * 256);
            float4 va = v4[lane];
            float4 vb = v4[lane + 32];
#pragma unroll
            for (int r0 = 0; r0 < 16; r0 += 8) {
                float4 c1[8], c2[8];
#pragma unroll
                for (int i = 0; i < 8; i++) {
                    const float4* r4 = (const float4*)(C + (size_t)(rbase + r0 + i) * 256);
                    c1[i] = __ldg(r4 + lane);
                    c2[i] = __ldg(r4 + lane + 32);
                }
                float s[8];
#pragma unroll
                for (int i = 0; i < 8; i++) {
                    s[i] = c1[i].x*va.x + c1[i].y*va.y + c1[i].z*va.z + c1[i].w*va.w
                         + c2[i].x*vb.x + c2[i].y*vb.y + c2[i].z*vb.z + c2[i].w*vb.w;
                }
#pragma unroll
                for (int o = 16; o; o >>= 1) {
#pragma unroll
                    for (int i = 0; i < 8; i++)
                        s[i] += __shfl_xor_sync(0xffffffffu, s[i], o);
                }
                if (lane < 8) wv[rbase + r0 + lane] = s[lane];
            }
        }
        __syncthreads();

        float a = blk_sum512((t < 256) ? V[j * 256 + t] * wv[t] : 0.f, red);
        if (t == 0) alpha[j] = a;

        float wnew = 0.f;
        if (t < 256) {
            wnew = wv[t] - a * V[j * 256 + t];
            if (j > 0) wnew -= beta[j - 1] * V[(j - 1) * 256 + t];
        }

        {
            __syncthreads();
            if (t < 256) wv[t] = wnew;
            __syncthreads();
            float4 wa = ((const float4*)wv)[lane];
            float4 wb = ((const float4*)wv)[lane + 32];
            {
                int i0 = wid * 4;
                if (i0 <= j) {
                    float s[4];
#pragma unroll
                    for (int q = 0; q < 4; q++) {
                        int iq = (i0 + q <= j) ? (i0 + q) : j;
                        const float4* vi4 = (const float4*)(V + iq * 256);
                        float4 c1 = vi4[lane], c2 = vi4[lane + 32];
                        s[q] = c1.x*wa.x + c1.y*wa.y + c1.z*wa.z + c1.w*wa.w
                             + c2.x*wb.x + c2.y*wb.y + c2.z*wb.z + c2.w*wb.w;
                    }
#pragma unroll
                    for (int o = 16; o; o >>= 1) {
                        s[0] += __shfl_xor_sync(0xffffffffu, s[0], o);
                        s[1] += __shfl_xor_sync(0xffffffffu, s[1], o);
                        s[2] += __shfl_xor_sync(0xffffffffu, s[2], o);
                        s[3] += __shfl_xor_sync(0xffffffffu, s[3], o);
                    }
                    if (lane == 0) {
#pragma unroll
                        for (int q = 0; q < 4; q++)
                            if (i0 + q <= j) coef[i0 + q] = s[q];
                    }
                }
            }
            __syncthreads();
            int ibeg = half ? ((j + 1) >> 1) : 0;
            int iend = half ? (j + 1) : ((j + 1) >> 1);
            float cr0 = 0.f, cr1 = 0.f, cr2 = 0.f, cr3 = 0.f;
            int i = ibeg;
            for (; i + 3 < iend; i += 4) {
                cr0 += coef[i]     * V[i * 256 + e];
                cr1 += coef[i + 1] * V[(i + 1) * 256 + e];
                cr2 += coef[i + 2] * V[(i + 2) * 256 + e];
                cr3 += coef[i + 3] * V[(i + 3) * 256 + e];
            }
            for (; i < iend; i++) cr0 += coef[i] * V[i * 256 + e];
            cbuf[t] = (cr0 + cr1) + (cr2 + cr3);
            __syncthreads();
            if (t < 256) wnew = wv[t] - (cbuf[t] + cbuf[t + 256]);
        }

        float b2 = blk_sum512((t < 256) ? wnew * wnew : 0.f, red);
        float bn = sqrtf(b2);
        if (bn < 1e-20f) { m_eff = j + 1; break; }
        if (t == 0) beta[j] = bn;
        if (t < 256) V[(j + 1) * 256 + t] = wnew / bn;
        __syncthreads();
    }

    int m = m_eff;

    float gl = 1e30f, gh = -1e30f;
    if (t < m) {
        float r = (t > 0 ? fabsf(beta[t - 1]) : 0.f) + (t < m - 1 ? fabsf(beta[t]) : 0.f);
        gl = alpha[t] - r;
        gh = alpha[t] + r;
    }
    float lo = blk_min512(gl, red);
    float hi = blk_max512(gh, red);

    if (t < m - 1) tdd[t] = beta[t] * beta[t];
    __syncthreads();

    for (int r = 0; r < 3; r++) {
        float xx = lo + (hi - lo) * ((float)(t + 1) * (1.f / 513.f));
        int cnt = 0;
        float d = alpha[0] - xx;
        if (d < 0.f) cnt++;
        for (int i = 1; i < m; i++) {
            if (fabsf(d) < 1e-30f) d = (d < 0.f) ? -1e-30f : 1e-30f;
            d = alpha[i] - xx - __fdividef(tdd[i - 1], d);
            if (d < 0.f) cnt++;
        }
        float cl = (cnt < m)  ? xx : -1e30f;
        float ch = (cnt >= m) ? xx :  1e30f;
        float nl = blk_max512(cl, red);
        float nh = blk_min512(ch, red);
        lo = fmaxf(lo, nl);
        hi = fminf(hi, nh);
    }
    float lam = 0.5f * (lo + hi);
    __syncthreads();

    if (t == 0) {
        for (int it = 0; it < 2; it++) {
            if (it == 0) for (int i = 0; i < m; i++) yv[i] = 1.f;
            for (int i = 0; i < m; i++) {
                tdd[i] = alpha[i] - lam;
                tu1[i] = (i < m - 1) ? beta[i] : 0.f;
                tu2[i] = 0.f;
            }
            for (int i = 0; i < m - 1; i++) {
                float p = tdd[i], q = tu1[i], rr = tu2[i];
                float s = beta[i];
                float uu = tdd[i + 1], vvv = tu1[i + 1];
                float yi = yv[i], yi1 = yv[i + 1];
                if (fabsf(s) > fabsf(p)) {
                    float tmp;
                    tmp = p; p = s; s = tmp;
                    tmp = q; q = uu; uu = tmp;
                    tmp = rr; rr = vvv; vvv = tmp;
                    tmp = yi; yi = yi1; yi1 = tmp;
                }
                if (p == 0.f) p = 1e-30f;
                float mf = s / p;
                tdd[i] = p; tu1[i] = q; tu2[i] = rr; yv[i] = yi;
                tdd[i + 1] = uu - mf * q;
                tu1[i + 1] = vvv - mf * rr;
                tu2[i + 1] = 0.f;
                yv[i + 1] = yi1 - mf * yi;
            }
            if (tdd[m - 1] == 0.f) tdd[m - 1] = 1e-30f;
            yv[m - 1] /= tdd[m - 1];
            if (m >= 2) yv[m - 2] = (yv[m - 2] - tu1[m - 2] * yv[m - 1]) / tdd[m - 2];
            for (int i = m - 3; i >= 0; i--)
                yv[i] = (yv[i] - tu1[i] * yv[i + 1] - tu2[i] * yv[i + 2]) / tdd[i];
            float s2 = 0.f;
            for (int i = 0; i < m; i++) s2 += yv[i] * yv[i];
            float inv = rsqrtf(s2);
            for (int i = 0; i < m; i++) yv[i] *= inv;
        }
        midx = 1 << 30;
    }
    __syncthreads();

    {
        int ibeg = half ? (m >> 1) : 0;
        int iend = half ? m : (m >> 1);
        float v0 = 0.f, v1 = 0.f, v2 = 0.f, v3 = 0.f;
        int i = ibeg;
        for (; i + 3 < iend; i += 4) {
            v0 += yv[i]     * V[i * 256 + e];
            v1 += yv[i + 1] * V[(i + 1) * 256 + e];
            v2 += yv[i + 2] * V[(i + 2) * 256 + e];
            v3 += yv[i + 3] * V[(i + 3) * 256 + e];
        }
        for (; i < iend; i++) v0 += yv[i] * V[i * 256 + e];
        cbuf[t] = (v0 + v1) + (v2 + v3);
    }
    __syncthreads();
    float vr = cbuf[e] + cbuf[e + 256];
    float n2 = blk_sum512((t < 256) ? vr * vr : 0.f, red);
    vr *= rsqrtf(n2);

    float av = (t < 256) ? fabsf(vr) : -1.f;
    float mx = blk_max512(av, red);
    if (t < 256 && av == mx) atomicMin(&midx, t);
    __syncthreads();
    if (t == midx) ssc[0] = (vr >= 0.f) ? 1.f : -1.f;
    __syncthreads();

    if (t < 256) out[(size_t)b * 256 + t] = vr * ssc[0];
}

// ---------------------------------------------------------------------------
extern "C" void kernel_launch(void* const* d_in, const int* in_sizes, int n_in,
                              void* d_out, int out_size)
{
    const float* caps = (const float*)d_in[0];   // (64, 2048, 16)
    const float* W    = (const float*)d_in[1];   // (2048, 16, 256)
    float* out        = (float*)d_out;           // (64, 16, 16)

    dim3 g1(NCAPS, 2);
    u_kernel<<<g1, 256>>>(caps, W);

    dim3 gs(32, 4, BATCH);
    split_kernel<<<gs, 256>>>();

    cudaFuncSetAttribute(syrk_mma_kernel, cudaFuncAttributeMaxDynamicSharedMemorySize, SYRK_SMEM);
    dim3 g2(3, KSPLIT, BATCH);
    syrk_mma_kernel<<<g2, 256, SYRK_SMEM>>>();

    dim3 gr(3, BATCH);
    reduce_kernel<<<gr, 256>>>();

    dim3 gm(4, 4, BATCH);
    mirror_kernel<<<gm, dim3(32, 8)>>>();

    size_t smem = ((MLAN + 1) * 256 + 256 + 512 + 7 * MLAN + NWARP + 8) * sizeof(float);
    cudaFuncSetAttribute(lanczos_kernel, cudaFuncAttributeMaxDynamicSharedMemorySize, (int)smem);
    lanczos_kernel<<<BATCH, 512, smem>>>(out);
}

// round 17
// speedup vs baseline: 1.1243x; 1.1243x over previous
#include <cuda_runtime.h>
#include <math.h>

#define BATCH 64
#define NCAPS 2048
#define IDIM 16
#define DOUT 256
#define MLAN 40
#define KSPLIT 3

typedef unsigned long long u64;

__device__ float g_u[(size_t)BATCH * NCAPS * DOUT];              // 134 MB
__device__ float g_C[(size_t)BATCH * DOUT * DOUT];               // 16 MB
__device__ float g_Cp[KSPLIT][(size_t)BATCH * DOUT * DOUT];      // 48 MB partials

// ---------------- packed f32x2 helpers ----------------
__device__ __forceinline__ void ffma2(u64 &d, u64 a, u64 b) {
    asm("fma.rn.f32x2 %0, %1, %2, %0;" : "+l"(d) : "l"(a), "l"(b));
}
__device__ __forceinline__ u64 pack2(float x, float y) {
    u64 r; asm("mov.b64 %0, {%1, %2};" : "=l"(r) : "f"(x), "f"(y)); return r;
}
__device__ __forceinline__ void unpack2(float &x, float &y, u64 v) {
    asm("mov.b64 {%0, %1}, %2;" : "=f"(x), "=f"(y) : "l"(v));
}

// ---------------------------------------------------------------------------
// Pass 1: u[b,c,o] = sum_i caps[b,c,i] * W[c,i,o]
// ---------------------------------------------------------------------------
__global__ void u_kernel(const float* __restrict__ caps, const float* __restrict__ W)
{
    int c  = blockIdx.x;
    int b0 = blockIdx.y * 32;
    __shared__ __align__(16) float caps_s[32][IDIM];
    __shared__ __align__(16) float w_s[IDIM][DOUT];
    int t = threadIdx.x;

    for (int idx = t; idx < 32 * IDIM; idx += 256) {
        int b = idx >> 4, i = idx & 15;
        caps_s[b][i] = caps[(size_t)(b0 + b) * (NCAPS * IDIM) + (size_t)c * IDIM + i];
    }
    for (int idx = t; idx < IDIM * DOUT; idx += 256)
        ((float*)w_s)[idx] = W[(size_t)c * (IDIM * DOUT) + idx];
    __syncthreads();

    float wr[IDIM];
#pragma unroll
    for (int i = 0; i < IDIM; i++) wr[i] = w_s[i][t];

#pragma unroll 4
    for (int b = 0; b < 32; b++) {
        const float4* cp = (const float4*)caps_s[b];
        float acc = 0.f;
#pragma unroll
        for (int q = 0; q < 4; q++) {
            float4 cv = cp[q];
            acc += cv.x * wr[q * 4 + 0] + cv.y * wr[q * 4 + 1]
                 + cv.z * wr[q * 4 + 2] + cv.w * wr[q * 4 + 3];
        }
        g_u[(size_t)(b0 + b) * (NCAPS * DOUT) + (size_t)c * DOUT + t] = acc;
    }
}

// ---------------------------------------------------------------------------
// Pass 2: SYRK, K-split x3, 3 symmetric tiles, packed f32x2 FMA.
// ---------------------------------------------------------------------------
#define BK 16
__global__ void __launch_bounds__(256, 2) syrk_kernel()
{
    int b = blockIdx.z;
    int which = blockIdx.x;
    int ks = blockIdx.y;
    int d0 = (which == 0) ? 0 : 128;
    int e0 = (which == 1) ? 128 : 0;
    int kbeg = ks * 688;
    int kend = (ks == KSPLIT - 1) ? NCAPS : kbeg + 688;

    __shared__ __align__(16) float As[BK][128];
    __shared__ __align__(16) float Bs[BK][128];
    int t = threadIdx.x;
    int tx = t & 15, ty = t >> 4;

    const float* ub = g_u + (size_t)b * NCAPS * DOUT;

    u64 acc2[8][4];
#pragma unroll
    for (int i = 0; i < 8; i++)
#pragma unroll
        for (int j = 0; j < 4; j++) acc2[i][j] = 0ull;

    for (int c0 = kbeg; c0 < kend; c0 += BK) {
#pragma unroll
        for (int l = 0; l < 2; l++) {
            int idx = t + l * 256;
            int r = idx >> 5, cc = (idx & 31) * 4;
            *(float4*)&As[r][cc] = *(const float4*)&ub[(size_t)(c0 + r) * DOUT + d0 + cc];
            *(float4*)&Bs[r][cc] = *(const float4*)&ub[(size_t)(c0 + r) * DOUT + e0 + cc];
        }
        __syncthreads();
#pragma unroll
        for (int k = 0; k < BK; k++) {
            float4 A1 = *(float4*)&As[k][ty * 8];
            float4 A2 = *(float4*)&As[k][ty * 8 + 4];
            float4 B1 = *(float4*)&Bs[k][tx * 8];
            float4 B2 = *(float4*)&Bs[k][tx * 8 + 4];
            u64 b2[4] = { pack2(B1.x, B1.y), pack2(B1.z, B1.w),
                          pack2(B2.x, B2.y), pack2(B2.z, B2.w) };
            float a[8] = {A1.x, A1.y, A1.z, A1.w, A2.x, A2.y, A2.z, A2.w};
#pragma unroll
            for (int i = 0; i < 8; i++) {
                u64 ad = pack2(a[i], a[i]);
#pragma unroll
                for (int j = 0; j < 4; j++) ffma2(acc2[i][j], ad, b2[j]);
            }
        }
        __syncthreads();
    }

    float* Cb = g_Cp[ks] + (size_t)b * DOUT * DOUT;
#pragma unroll
    for (int i = 0; i < 8; i++) {
        int d = d0 + ty * 8 + i;
        float v[8];
#pragma unroll
        for (int j = 0; j < 4; j++) unpack2(v[2 * j], v[2 * j + 1], acc2[i][j]);
        *(float4*)&Cb[(size_t)d * DOUT + e0 + tx * 8]     = make_float4(v[0], v[1], v[2], v[3]);
        *(float4*)&Cb[(size_t)d * DOUT + e0 + tx * 8 + 4] = make_float4(v[4], v[5], v[6], v[7]);
    }
}

// sum the 3 K-split partials (deterministic)
__global__ void reduce_kernel()
{
    int b = blockIdx.y;
    int which = blockIdx.x;
    int d0 = (which == 0) ? 0 : 128;
    int e0 = (which == 1) ? 128 : 0;
    size_t base = (size_t)b * DOUT * DOUT;
    int t = threadIdx.x;
    for (int i = t; i < 128 * 32; i += 256) {
        int r = i >> 5, c4 = (i & 31);
        size_t off = base + (size_t)(d0 + r) * DOUT + e0 + c4 * 4;
        float4 a = *(const float4*)&g_Cp[0][off];
        float4 bb = *(const float4*)&g_Cp[1][off];
        float4 c = *(const float4*)&g_Cp[2][off];
        float4 s = make_float4(a.x + bb.x + c.x, a.y + bb.y + c.y,
                               a.z + bb.z + c.z, a.w + bb.w + c.w);
        *(float4*)&g_C[off] = s;
    }
}

// mirror (1,0) tile into (0,1)
__global__ void mirror_kernel()
{
    __shared__ float tile[32][33];
    float* Cb = g_C + (size_t)blockIdx.z * DOUT * DOUT;
    int sx = 128 + blockIdx.x * 32;
    int sy = blockIdx.y * 32;
    int tx = threadIdx.x, ty = threadIdx.y;
#pragma unroll
    for (int k = 0; k < 32; k += 8)
        tile[ty + k][tx] = Cb[(size_t)(sx + ty + k) * DOUT + sy + tx];
    __syncthreads();
#pragma unroll
    for (int k = 0; k < 32; k += 8)
        Cb[(size_t)(sy + ty + k) * DOUT + sx + tx] = tile[tx][ty + k];
}

// ---------------------------------------------------------------------------
// Pass 3: Lanczos(m=40), 1024 threads/block, CGS1, parallel Sturm.
// ---------------------------------------------------------------------------
#define NWARP 32
__device__ __forceinline__ float blk_sum1k(float v, float* red)
{
#pragma unroll
    for (int o = 16; o; o >>= 1) v += __shfl_xor_sync(0xffffffffu, v, o);
    int lane = threadIdx.x & 31, wid = threadIdx.x >> 5;
    __syncthreads();
    if (lane == 0) red[wid] = v;
    __syncthreads();
    float s = red[0];
#pragma unroll
    for (int i = 1; i < NWARP; i++) s += red[i];
    return s;
}

__device__ __forceinline__ float blk_max1k(float v, float* red)
{
#pragma unroll
    for (int o = 16; o; o >>= 1) v = fmaxf(v, __shfl_xor_sync(0xffffffffu, v, o));
    int lane = threadIdx.x & 31, wid = threadIdx.x >> 5;
    __syncthreads();
    if (lane == 0) red[wid] = v;
    __syncthreads();
    float s = red[0];
#pragma unroll
    for (int i = 1; i < NWARP; i++) s = fmaxf(s, red[i]);
    return s;
}

__device__ __forceinline__ float blk_min1k(float v, float* red)
{
#pragma unroll
    for (int o = 16; o; o >>= 1) v = fminf(v, __shfl_xor_sync(0xffffffffu, v, o));
    int lane = threadIdx.x & 31, wid = threadIdx.x >> 5;
    __syncthreads();
    if (lane == 0) red[wid] = v;
    __syncthreads();
    float s = red[0];
#pragma unroll
    for (int i = 1; i < NWARP; i++) s = fminf(s, red[i]);
    return s;
}

__global__ void __launch_bounds__(1024, 1) lanczos_kernel(float* __restrict__ out)
{
    extern __shared__ float sh[];
    float* V     = sh;                        // (MLAN+1) x 256
    float* wv    = V + (MLAN + 1) * 256;      // 256
    float* cbuf  = wv + 256;                  // 1024
    float* alpha = cbuf + 1024;               // MLAN
    float* beta  = alpha + MLAN;              // MLAN
    float* coef  = beta + MLAN;               // MLAN
    float* yv    = coef + MLAN;               // MLAN
    float* tdd   = yv + MLAN;                 // MLAN
    float* tu1   = tdd + MLAN;                // MLAN
    float* tu2   = tu1 + MLAN;                // MLAN
    float* red   = tu2 + MLAN;                // NWARP
    float* ssc   = red + NWARP;               // 8

    __shared__ int midx;

    int t = threadIdx.x;
    int lane = t & 31, wid = t >> 5;
    int e = t & 255;
    int quarter = t >> 8;                     // 0..3
    int b = blockIdx.x;
    const float* C = g_C + (size_t)b * DOUT * DOUT;

    float x = __sinf((float)e * 1.7f + 0.5f) + 0.01f;
    float nn = blk_sum1k((t < 256) ? x * x : 0.f, red);
    x *= rsqrtf(nn);
    if (t < 256) V[t] = x;
    __syncthreads();

    int m_eff = MLAN;
    int rbase = wid * 8;                      // 32 warps x 8 rows = 256
    for (int j = 0; j < MLAN; j++) {
        // ---- matvec: wv = C*V[j]; one pass, 8 rows/warp in 2 LDG windows ----
        {
            const float4* v4 = (const float4*)(V + j * 256);
            float4 va = v4[lane];
            float4 vb = v4[lane + 32];
            float s[8];
#pragma unroll
            for (int g = 0; g < 2; g++) {
                float4 c1[4], c2[4];
#pragma unroll
                for (int i = 0; i < 4; i++) {
                    const float4* r4 = (const float4*)(C + (size_t)(rbase + g * 4 + i) * 256);
                    c1[i] = __ldg(r4 + lane);
                    c2[i] = __ldg(r4 + lane + 32);
                }
#pragma unroll
                for (int i = 0; i < 4; i++) {
                    s[g * 4 + i] =
                          c1[i].x*va.x + c1[i].y*va.y + c1[i].z*va.z + c1[i].w*va.w
                        + c2[i].x*vb.x + c2[i].y*vb.y + c2[i].z*vb.z + c2[i].w*vb.w;
                }
            }
#pragma unroll
            for (int o = 16; o; o >>= 1) {
#pragma unroll
                for (int i = 0; i < 8; i++)
                    s[i] += __shfl_xor_sync(0xffffffffu, s[i], o);
            }
            if (lane < 8) wv[rbase + lane] = s[lane];
        }
        __syncthreads();

        float a = blk_sum1k((t < 256) ? V[j * 256 + t] * wv[t] : 0.f, red);
        if (t == 0) alpha[j] = a;

        float wnew = 0.f;
        if (t < 256) {
            wnew = wv[t] - a * V[j * 256 + t];
            if (j > 0) wnew -= beta[j - 1] * V[(j - 1) * 256 + t];
        }

        // ---- CGS1 full reorth: 32 warps x 2 dots = one round ----
        {
            __syncthreads();
            if (t < 256) wv[t] = wnew;
            __syncthreads();
            float4 wa = ((const float4*)wv)[lane];
            float4 wb = ((const float4*)wv)[lane + 32];
            int i0 = wid * 2;
            if (i0 <= j) {
                float s[2];
#pragma unroll
                for (int q = 0; q < 2; q++) {
                    int iq = (i0 + q <= j) ? (i0 + q) : j;
                    const float4* vi4 = (const float4*)(V + iq * 256);
                    float4 c1 = vi4[lane], c2 = vi4[lane + 32];
                    s[q] = c1.x*wa.x + c1.y*wa.y + c1.z*wa.z + c1.w*wa.w
                         + c2.x*wb.x + c2.y*wb.y + c2.z*wb.z + c2.w*wb.w;
                }
#pragma unroll
                for (int o = 16; o; o >>= 1) {
                    s[0] += __shfl_xor_sync(0xffffffffu, s[0], o);
                    s[1] += __shfl_xor_sync(0xffffffffu, s[1], o);
                }
                if (lane == 0) {
                    coef[i0] = s[0];
                    if (i0 + 1 <= j) coef[i0 + 1] = s[1];
                }
            }
            __syncthreads();
            // 4-way split axpy
            int n = j + 1;
            int ibeg = (quarter * n) >> 2;
            int iend = ((quarter + 1) * n) >> 2;
            float cr0 = 0.f, cr1 = 0.f;
            int i = ibeg;
            for (; i + 1 < iend; i += 2) {
                cr0 += coef[i]     * V[i * 256 + e];
                cr1 += coef[i + 1] * V[(i + 1) * 256 + e];
            }
            for (; i < iend; i++) cr0 += coef[i] * V[i * 256 + e];
            cbuf[t] = cr0 + cr1;
            __syncthreads();
            if (t < 256)
                wnew = wv[t] - ((cbuf[t] + cbuf[t + 256]) + (cbuf[t + 512] + cbuf[t + 768]));
        }

        float b2 = blk_sum1k((t < 256) ? wnew * wnew : 0.f, red);
        float bn = sqrtf(b2);
        if (bn < 1e-20f) { m_eff = j + 1; break; }
        if (t == 0) beta[j] = bn;
        if (t < 256) V[(j + 1) * 256 + t] = wnew / bn;
        __syncthreads();
    }

    int m = m_eff;

    // ---- Gershgorin bounds ----
    float gl = 1e30f, gh = -1e30f;
    if (t < m) {
        float r = (t > 0 ? fabsf(beta[t - 1]) : 0.f) + (t < m - 1 ? fabsf(beta[t]) : 0.f);
        gl = alpha[t] - r;
        gh = alpha[t] + r;
    }
    float lo = blk_min1k(gl, red);
    float hi = blk_max1k(gh, red);

    if (t < m - 1) tdd[t] = beta[t] * beta[t];
    __syncthreads();

    // ---- parallel Sturm: 1024 points x 2 rounds ----
    for (int r = 0; r < 2; r++) {
        float xx = lo + (hi - lo) * ((float)(t + 1) * (1.f / 1025.f));
        int cnt = 0;
        float d = alpha[0] - xx;
        if (d < 0.f) cnt++;
        for (int i = 1; i < m; i++) {
            if (fabsf(d) < 1e-30f) d = (d < 0.f) ? -1e-30f : 1e-30f;
            d = alpha[i] - xx - __fdividef(tdd[i - 1], d);
            if (d < 0.f) cnt++;
        }
        float cl = (cnt < m)  ? xx : -1e30f;
        float ch = (cnt >= m) ? xx :  1e30f;
        float nl = blk_max1k(cl, red);
        float nh = blk_min1k(ch, red);
        lo = fmaxf(lo, nl);
        hi = fminf(hi, nh);
    }
    float lam = 0.5f * (lo + hi);
    __syncthreads();

    // ---- inverse iteration (serial, thread 0) ----
    if (t == 0) {
        for (int it = 0; it < 2; it++) {
            if (it == 0) for (int i = 0; i < m; i++) yv[i] = 1.f;
            for (int i = 0; i < m; i++) {
                tdd[i] = alpha[i] - lam;
                tu1[i] = (i < m - 1) ? beta[i] : 0.f;
                tu2[i] = 0.f;
            }
            for (int i = 0; i < m - 1; i++) {
                float p = tdd[i], q = tu1[i], rr = tu2[i];
                float s = beta[i];
                float uu = tdd[i + 1], vvv = tu1[i + 1];
                float yi = yv[i], yi1 = yv[i + 1];
                if (fabsf(s) > fabsf(p)) {
                    float tmp;
                    tmp = p; p = s; s = tmp;
                    tmp = q; q = uu; uu = tmp;
                    tmp = rr; rr = vvv; vvv = tmp;
                    tmp = yi; yi = yi1; yi1 = tmp;
                }
                if (p == 0.f) p = 1e-30f;
                float mf = s / p;
                tdd[i] = p; tu1[i] = q; tu2[i] = rr; yv[i] = yi;
                tdd[i + 1] = uu - mf * q;
                tu1[i + 1] = vvv - mf * rr;
                tu2[i + 1] = 0.f;
                yv[i + 1] = yi1 - mf * yi;
            }
            if (tdd[m - 1] == 0.f) tdd[m - 1] = 1e-30f;
            yv[m - 1] /= tdd[m - 1];
            if (m >= 2) yv[m - 2] = (yv[m - 2] - tu1[m - 2] * yv[m - 1]) / tdd[m - 2];
            for (int i = m - 3; i >= 0; i--)
                yv[i] = (yv[i] - tu1[i] * yv[i + 1] - tu2[i] * yv[i + 2]) / tdd[i];
            float s2 = 0.f;
            for (int i = 0; i < m; i++) s2 += yv[i] * yv[i];
            float inv = rsqrtf(s2);
            for (int i = 0; i < m; i++) yv[i] *= inv;
        }
        midx = 1 << 30;
    }
    __syncthreads();

    // ---- Ritz vector (4-way split) ----
    {
        int ibeg = (quarter * m) >> 2;
        int iend = ((quarter + 1) * m) >> 2;
        float v0 = 0.f, v1 = 0.f;
        int i = ibeg;
        for (; i + 1 < iend; i += 2) {
            v0 += yv[i]     * V[i * 256 + e];
            v1 += yv[i + 1] * V[(i + 1) * 256 + e];
        }
        for (; i < iend; i++) v0 += yv[i] * V[i * 256 + e];
        cbuf[t] = v0 + v1;
    }
    __syncthreads();
    float vr = (cbuf[e] + cbuf[e + 256]) + (cbuf[e + 512] + cbuf[e + 768]);
    float n2 = blk_sum1k((t < 256) ? vr * vr : 0.f, red);
    vr *= rsqrtf(n2);

    float av = (t < 256) ? fabsf(vr) : -1.f;
    float mx = blk_max1k(av, red);
    if (t < 256 && av == mx) atomicMin(&midx, t);
    __syncthreads();
    if (t == midx) ssc[0] = (vr >= 0.f) ? 1.f : -1.f;
    __syncthreads();

    if (t < 256) out[(size_t)b * 256 + t] = vr * ssc[0];
}

// ---------------------------------------------------------------------------
extern "C" void kernel_launch(void* const* d_in, const int* in_sizes, int n_in,
                              void* d_out, int out_size)
{
    const float* caps = (const float*)d_in[0];   // (64, 2048, 16)
    const float* W    = (const float*)d_in[1];   // (2048, 16, 256)
    float* out        = (float*)d_out;           // (64, 16, 16)

    dim3 g1(NCAPS, 2);
    u_kernel<<<g1, 256>>>(caps, W);

    dim3 g2(3, KSPLIT, BATCH);
    syrk_kernel<<<g2, 256>>>();

    dim3 gr(3, BATCH);
    reduce_kernel<<<gr, 256>>>();

    dim3 gm(4, 4, BATCH);
    mirror_kernel<<<gm, dim3(32, 8)>>>();

    size_t smem = ((MLAN + 1) * 256 + 256 + 1024 + 7 * MLAN + NWARP + 8) * sizeof(float);
    cudaFuncSetAttribute(lanczos_kernel, cudaFuncAttributeMaxDynamicSharedMemorySize, (int)smem);
    lanczos_kernel<<<BATCH, 1024, smem>>>(out);
}